// round 16
// baseline (speedup 1.0000x reference)
#include <cuda_runtime.h>
#include <cuda_fp16.h>
#include <cstdint>

// -------------------- problem dims --------------------
#define BATCH   4
#define SEQ     2048
#define DMODEL  1024
#define HEADS   16
#define HDIM    64
#define MROWS   (BATCH*SEQ)         // 8192
#define NBH     (BATCH*HEADS)       // 64
#define NQKV    (3*DMODEL)          // 3072
#define LOG2E   1.4426950408889634f

// -------------------- device scratch (static, no allocs) --------------------
__device__ __half g_Xh   [(size_t)MROWS * DMODEL];
__device__ __half g_WTqkv[(size_t)NQKV * DMODEL];     // rows: [Wq*log2e/32 | Wk | Wv] transposed
__device__ float  g_bqkv [NQKV];                      // [bq*log2e/32 | bk | bv]
__device__ __half g_WTo  [(size_t)DMODEL * DMODEL];
__device__ __half g_QKV  [(size_t)MROWS * NQKV];      // cols: [Q(scaled) | K | V]
__device__ __half g_Ctx  [(size_t)MROWS * DMODEL];

// -------------------- small helpers --------------------
__device__ __forceinline__ uint32_t smem_u32(const void* p) {
    uint32_t a;
    asm("{ .reg .u64 t; cvta.to.shared.u64 t, %1; cvt.u32.u64 %0, t; }" : "=r"(a) : "l"(p));
    return a;
}
__device__ __forceinline__ void cp16(void* s, const void* g) {
    uint32_t sa = smem_u32(s);
    asm volatile("cp.async.cg.shared.global [%0], [%1], 16;" :: "r"(sa), "l"(g) : "memory");
}
__device__ __forceinline__ void cp16_ca(void* s, const void* g) {   // L1-allocating
    uint32_t sa = smem_u32(s);
    asm volatile("cp.async.ca.shared.global [%0], [%1], 16;" :: "r"(sa), "l"(g) : "memory");
}
#define CP_COMMIT() asm volatile("cp.async.commit_group;" ::: "memory")
#define CP_WAIT0()  asm volatile("cp.async.wait_group 0;" ::: "memory")
#define CP_WAIT1()  asm volatile("cp.async.wait_group 1;" ::: "memory")

__device__ __forceinline__ void ldsm_x4(uint32_t* r, const void* p) {
    uint32_t a = smem_u32(p);
    asm volatile("ldmatrix.sync.aligned.m8n8.x4.shared.b16 {%0,%1,%2,%3}, [%4];"
                 : "=r"(r[0]), "=r"(r[1]), "=r"(r[2]), "=r"(r[3]) : "r"(a));
}
__device__ __forceinline__ void ldsm_x4_t(uint32_t* r, const void* p) {
    uint32_t a = smem_u32(p);
    asm volatile("ldmatrix.sync.aligned.m8n8.x4.trans.shared.b16 {%0,%1,%2,%3}, [%4];"
                 : "=r"(r[0]), "=r"(r[1]), "=r"(r[2]), "=r"(r[3]) : "r"(a));
}
__device__ __forceinline__ void mma16816(float* c, const uint32_t* a, const uint32_t* b) {
    asm volatile("mma.sync.aligned.m16n8k16.row.col.f32.f16.f16.f32 "
                 "{%0,%1,%2,%3}, {%4,%5,%6,%7}, {%8,%9}, {%0,%1,%2,%3};"
                 : "+f"(c[0]), "+f"(c[1]), "+f"(c[2]), "+f"(c[3])
                 : "r"(a[0]), "r"(a[1]), "r"(a[2]), "r"(a[3]), "r"(b[0]), "r"(b[1]));
}
// f16-accumulator variant: C/D are 2 regs of packed half2
__device__ __forceinline__ void mma16816h(uint32_t* c, const uint32_t* a, const uint32_t* b) {
    asm volatile("mma.sync.aligned.m16n8k16.row.col.f16.f16.f16.f16 "
                 "{%0,%1}, {%2,%3,%4,%5}, {%6,%7}, {%0,%1};"
                 : "+r"(c[0]), "+r"(c[1])
                 : "r"(a[0]), "r"(a[1]), "r"(a[2]), "r"(a[3]), "r"(b[0]), "r"(b[1]));
}
__device__ __forceinline__ void h2exp2(uint32_t& v) {
    asm("ex2.approx.f16x2 %0, %0;" : "+r"(v));
}

// -------------------- mma.sync GEMM: BK=64, 3-stage, fully unrolled K --------------------
#define LDS 72          // 64 + 8 pad halves; ldmatrix conflict-free
#define STAGES 3
#define CHUNKS 16       // K = 1024 = 16 * 64 (compile-time)

template<bool OUT_HALF>
__global__ __launch_bounds__(256, 2) void mma_gemm(
    const __half* __restrict__ A, const __half* __restrict__ B,
    const float* __restrict__ bias, float* __restrict__ Cf, __half* __restrict__ Ch,
    int lda, int ldb, int ldc)
{
    extern __shared__ __half sh[];
    __half* sA = sh;                        // [STAGES][128][LDS]
    __half* sB = sh + STAGES * 128 * LDS;

    const int tid = threadIdx.x;
    const int lane = tid & 31;
    const int w = tid >> 5;
    const int wm = w >> 2;
    const int wn = w & 3;

    const __half* Ab = A + (long long)blockIdx.y * 128 * lda;
    const __half* Bb = B + (long long)blockIdx.x * 128 * ldb;

    auto loadStage = [&](int s, int k0) {
        __half* a0 = sA + s * 128 * LDS;
        __half* b0 = sB + s * 128 * LDS;
#pragma unroll
        for (int i = tid; i < 128 * 8; i += 256) {
            int row = i >> 3, c8 = (i & 7) * 8;
            cp16_ca(a0 + row * LDS + c8, Ab + (long long)row * lda + k0 + c8);  // A: L1-cached
            cp16(b0 + row * LDS + c8, Bb + (long long)row * ldb + k0 + c8);     // B: L2-only
        }
    };

    float acc[4][4][4];
#pragma unroll
    for (int mt = 0; mt < 4; mt++)
#pragma unroll
        for (int nt = 0; nt < 4; nt++)
#pragma unroll
            for (int j = 0; j < 4; j++) acc[mt][nt][j] = 0.f;

    loadStage(0, 0);  CP_COMMIT();
    loadStage(1, 64); CP_COMMIT();

#pragma unroll
    for (int i = 0; i < CHUNKS; i++) {
        CP_WAIT1();
        __syncthreads();

        const int s = i % STAGES;                 // compile-time after unroll
        __half* a0 = sA + s * 128 * LDS;
        __half* b0 = sB + s * 128 * LDS;

#pragma unroll
        for (int kk = 0; kk < 64; kk += 16) {
            uint32_t af[4][4];
#pragma unroll
            for (int mt = 0; mt < 4; mt++)
                ldsm_x4(af[mt], a0 + (wm * 64 + mt * 16 + (lane & 15)) * LDS + kk + (lane >> 4) * 8);

            uint32_t bf[4][2];
#pragma unroll
            for (int p = 0; p < 2; p++) {
                uint32_t r[4];
                ldsm_x4(r, b0 + (wn * 32 + p * 16 + (lane & 7) + ((lane >> 4) & 1) * 8) * LDS
                              + kk + ((lane >> 3) & 1) * 8);
                bf[2 * p][0] = r[0]; bf[2 * p][1] = r[1];
                bf[2 * p + 1][0] = r[2]; bf[2 * p + 1][1] = r[3];
            }
#pragma unroll
            for (int mt = 0; mt < 4; mt++)
#pragma unroll
                for (int nt = 0; nt < 4; nt++)
                    mma16816(acc[mt][nt], af[mt], bf[nt]);

            // issue next-stage prefetch AFTER the first kk-step's MMAs so the
            // tensor pipe starts immediately post-barrier; ALU/LSU burst overlaps MMA.
            if (kk == 0) {
                if (i + 2 < CHUNKS) loadStage((i + 2) % STAGES, (i + 2) * 64);
                CP_COMMIT();
            }
        }
    }

#pragma unroll
    for (int mt = 0; mt < 4; mt++) {
        const int gRow0 = blockIdx.y * 128 + wm * 64 + mt * 16 + (lane >> 2);
#pragma unroll
        for (int nt = 0; nt < 4; nt++) {
            const int gCol = blockIdx.x * 128 + wn * 32 + nt * 8 + (lane & 3) * 2;
            float b0 = bias[gCol], b1 = bias[gCol + 1];
            float v00 = acc[mt][nt][0] + b0;
            float v01 = acc[mt][nt][1] + b1;
            float v10 = acc[mt][nt][2] + b0;
            float v11 = acc[mt][nt][3] + b1;
            if (OUT_HALF) {
                __half2* p0 = (__half2*)(Ch + (long long)gRow0 * ldc + gCol);
                __half2* p1 = (__half2*)(Ch + (long long)(gRow0 + 8) * ldc + gCol);
                *p0 = __floats2half2_rn(v00, v01);
                *p1 = __floats2half2_rn(v10, v11);
            } else {
                float2* p0 = (float2*)(Cf + (long long)gRow0 * ldc + gCol);
                float2* p1 = (float2*)(Cf + (long long)(gRow0 + 8) * ldc + gCol);
                *p0 = make_float2(v00, v01);
                *p1 = make_float2(v10, v11);
            }
        }
    }
}

// -------------------- fused flash attention: KTILE=64, 2-stage, late prefetch --------------------
// QK in fp16 accumulators (C-layout == PV A-layout), exp2 via f16x2 in place,
// row sums via fp32 ones-MMA. Prefetch issued after the QK phase.
__global__ __launch_bounds__(256, 2) void flash_mma(
    const __half* __restrict__ QKV, __half* __restrict__ Ctx)
{
    __shared__ __align__(16) __half sK[2][64][72];
    __shared__ __align__(16) __half sV[2][64][72];

    const int tid = threadIdx.x, lane = tid & 31, w = tid >> 5;
    const int z = blockIdx.y, b = z / HEADS, h = z % HEADS;
    const int qt = blockIdx.x;
    const __half* Qb = QKV + (size_t)(b * SEQ + qt * 128) * NQKV + h * HDIM;
    const __half* Kb = QKV + (size_t)(b * SEQ) * NQKV + DMODEL + h * HDIM;
    const __half* Vb = QKV + (size_t)(b * SEQ) * NQKV + 2 * DMODEL + h * HDIM;

    __half (*sQ)[72] = (__half (*)[72])&sK[0][0][0];
    for (int i = tid; i < 128 * 8; i += 256) {
        int row = i >> 3, c8 = (i & 7) * 8;
        cp16(&sQ[row][c8], Qb + (size_t)row * NQKV + c8);
    }
    CP_COMMIT(); CP_WAIT0();
    __syncthreads();
    uint32_t qf[4][4];
#pragma unroll
    for (int kk = 0; kk < 4; kk++)
        ldsm_x4(qf[kk], &sQ[w * 16 + (lane & 15)][kk * 16 + (lane >> 4) * 8]);
    __syncthreads();

    float acc[8][4];
#pragma unroll
    for (int j = 0; j < 8; j++)
#pragma unroll
        for (int t = 0; t < 4; t++) acc[j][t] = 0.f;
    float sumacc[4] = {0.f, 0.f, 0.f, 0.f};
    const uint32_t ones2 = 0x3C003C00u;              // half2(1,1)
    const uint32_t onesb[2] = {ones2, ones2};

    auto loadKV = [&](int s, int kt) {
        const __half* Kt = Kb + (size_t)kt * 64 * NQKV;
        const __half* Vt = Vb + (size_t)kt * 64 * NQKV;
        for (int i = tid; i < 64 * 8; i += 256) {
            int row = i >> 3, c8 = (i & 7) * 8;
            cp16(&sK[s][row][c8], Kt + (size_t)row * NQKV + c8);
            cp16(&sV[s][row][c8], Vt + (size_t)row * NQKV + c8);
        }
    };
    loadKV(0, 0); CP_COMMIT();

    for (int kt = 0; kt < SEQ / 64; kt++) {
        CP_WAIT0();
        __syncthreads();
        const int s = kt & 1;

        // ---- QK scores in fp16 accumulators ----
        uint32_t scH[8][2];
#pragma unroll
        for (int j = 0; j < 8; j++) { scH[j][0] = 0u; scH[j][1] = 0u; }
#pragma unroll
        for (int kk = 0; kk < 4; kk++) {
#pragma unroll
            for (int p = 0; p < 4; p++) {
                uint32_t r[4];
                ldsm_x4(r, &sK[s][p * 16 + (lane & 7) + ((lane >> 4) & 1) * 8]
                              [kk * 16 + ((lane >> 3) & 1) * 8]);
                uint32_t b0[2] = {r[0], r[1]}, b1[2] = {r[2], r[3]};
                mma16816h(scH[2 * p], qf[kk], b0);
                mma16816h(scH[2 * p + 1], qf[kk], b1);
            }
        }

        // prefetch next K/V AFTER the QK phase (tensor pipe busy from barrier+0)
        if (kt + 1 < SEQ / 64) loadKV(s ^ 1, kt + 1);
        CP_COMMIT();

        // ---- exp2 in place (scores already in PV A-fragment layout) ----
        uint32_t pf[4][4];
#pragma unroll
        for (int kk = 0; kk < 4; kk++) {
            uint32_t v0 = scH[2 * kk][0], v1 = scH[2 * kk][1];
            uint32_t v2 = scH[2 * kk + 1][0], v3 = scH[2 * kk + 1][1];
            h2exp2(v0); h2exp2(v1); h2exp2(v2); h2exp2(v3);
            pf[kk][0] = v0; pf[kk][1] = v1; pf[kk][2] = v2; pf[kk][3] = v3;
        }
#pragma unroll
        for (int kk = 0; kk < 4; kk++)
            mma16816(sumacc, pf[kk], onesb);

#pragma unroll
        for (int kk = 0; kk < 4; kk++) {
#pragma unroll
            for (int p = 0; p < 4; p++) {
                uint32_t r[4];
                ldsm_x4_t(r, &sV[s][kk * 16 + (lane & 15)][p * 16 + (lane >> 4) * 8]);
                uint32_t b0[2] = {r[0], r[1]}, b1[2] = {r[2], r[3]};
                mma16816(acc[2 * p], pf[kk], b0);
                mma16816(acc[2 * p + 1], pf[kk], b1);
            }
        }
    }

    const float inv0 = 1.0f / sumacc[0], inv1 = 1.0f / sumacc[2];

    const int gr = b * SEQ + qt * 128 + w * 16 + (lane >> 2);
    const int gc0 = h * HDIM + (lane & 3) * 2;
#pragma unroll
    for (int j = 0; j < 8; j++) {
        __half* r0 = Ctx + (size_t)gr * DMODEL + gc0 + j * 8;
        __half* r1 = Ctx + (size_t)(gr + 8) * DMODEL + gc0 + j * 8;
        *(__half2*)r0 = __floats2half2_rn(acc[j][0] * inv0, acc[j][1] * inv0);
        *(__half2*)r1 = __floats2half2_rn(acc[j][2] * inv1, acc[j][3] * inv1);
    }
}

// -------------------- converts (single launch) --------------------
__global__ void conv_all_kernel(
    const float* __restrict__ X,
    const float* __restrict__ Wq, const float* __restrict__ Wk,
    const float* __restrict__ Wv, const float* __restrict__ Wo,
    const float* __restrict__ bq, const float* __restrict__ bk,
    const float* __restrict__ bv,
    __half* __restrict__ Xh,
    __half* __restrict__ WTqkv, __half* __restrict__ WTo,
    float* __restrict__ bqkv)
{
    const int zz = blockIdx.z;
    const int tloc = threadIdx.y * 32 + threadIdx.x;
    if (zz == 5) {
        const int nF4 = MROWS * DMODEL / 4;
        const int stride = 32 * 32 * 256;
        for (int i = (blockIdx.y * 32 + blockIdx.x) * 256 + tloc; i < nF4; i += stride) {
            float4 x = ((const float4*)X)[i];
            __half2 a = __floats2half2_rn(x.x, x.y);
            __half2 c = __floats2half2_rn(x.z, x.w);
            ((uint2*)Xh)[i] = make_uint2(*(uint32_t*)&a, *(uint32_t*)&c);
        }
        return;
    }
    if (zz == 4) {
        int i = (blockIdx.y * 32 + blockIdx.x) * 256 + tloc;
        if (i < DMODEL)            bqkv[i] = bq[i] * (LOG2E / 32.0f);
        else if (i < 2 * DMODEL)   bqkv[i] = bk[i - DMODEL];
        else if (i < 3 * DMODEL)   bqkv[i] = bv[i - 2 * DMODEL];
        return;
    }
    const float* W = (zz == 0) ? Wq : (zz == 1) ? Wk : (zz == 2) ? Wv : Wo;
    __half* WT = (zz == 3) ? WTo : WTqkv + (size_t)zz * DMODEL * DMODEL;
    const float scale = (zz == 0) ? (LOG2E / 32.0f) : 1.0f;

    __shared__ float tile[32][33];
    const int tx = threadIdx.x, ty = threadIdx.y;
    const int k0 = blockIdx.y * 32, n0 = blockIdx.x * 32;
#pragma unroll
    for (int j = 0; j < 4; j++)
        tile[ty + j * 8][tx] = W[(size_t)(k0 + ty + j * 8) * DMODEL + n0 + tx];
    __syncthreads();
#pragma unroll
    for (int j = 0; j < 4; j++) {
        int n = n0 + ty + j * 8, k = k0 + tx;
        WT[(size_t)n * DMODEL + k] = __float2half_rn(tile[tx][ty + j * 8] * scale);
    }
}

// -------------------- launch --------------------
extern "C" void kernel_launch(void* const* d_in, const int* in_sizes, int n_in,
                              void* d_out, int out_size)
{
    const float* X  = (const float*)d_in[0];
    const float* Wq = (const float*)d_in[1];
    const float* bq = (const float*)d_in[2];
    const float* Wk = (const float*)d_in[3];
    const float* bk = (const float*)d_in[4];
    const float* Wv = (const float*)d_in[5];
    const float* bv = (const float*)d_in[6];
    const float* Wo = (const float*)d_in[7];
    const float* bo = (const float*)d_in[8];
    float* out = (float*)d_out;

    __half *pXh, *pWTqkv, *pWTo, *pQKV, *pCtx;
    float *pbqkv;
    cudaGetSymbolAddress((void**)&pXh, g_Xh);
    cudaGetSymbolAddress((void**)&pWTqkv, g_WTqkv);
    cudaGetSymbolAddress((void**)&pbqkv, g_bqkv);
    cudaGetSymbolAddress((void**)&pWTo, g_WTo);
    cudaGetSymbolAddress((void**)&pQKV, g_QKV);
    cudaGetSymbolAddress((void**)&pCtx, g_Ctx);

    const int GEMM_SMEM = STAGES * 2 * 128 * LDS * (int)sizeof(__half);  // 110592
    cudaFuncSetAttribute(mma_gemm<true>,  cudaFuncAttributeMaxDynamicSharedMemorySize, GEMM_SMEM);
    cudaFuncSetAttribute(mma_gemm<false>, cudaFuncAttributeMaxDynamicSharedMemorySize, GEMM_SMEM);

    // converts (1 launch)
    dim3 cgrid(32, 32, 6), cblk(32, 8);
    conv_all_kernel<<<cgrid, cblk>>>(X, Wq, Wk, Wv, Wo, bq, bk, bv,
                                     pXh, pWTqkv, pWTo, pbqkv);

    // fused QKV projection
    dim3 pg(NQKV / 128, MROWS / 128, 1);
    mma_gemm<true><<<pg, 256, GEMM_SMEM>>>(pXh, pWTqkv, pbqkv, nullptr, pQKV,
        DMODEL, DMODEL, NQKV);

    // fused flash attention -> fp16 Ctx
    dim3 fg(SEQ / 128, NBH);
    flash_mma<<<fg, 256>>>(pQKV, pCtx);

    // out = Ctx @ Wo + bo
    dim3 og(DMODEL / 128, MROWS / 128, 1);
    mma_gemm<false><<<og, 256, GEMM_SMEM>>>(pCtx, pWTo, bo, out, nullptr,
        DMODEL, DMODEL, DMODEL);
}

// round 17
// speedup vs baseline: 1.1660x; 1.1660x over previous
#include <cuda_runtime.h>
#include <cuda_fp16.h>
#include <cstdint>

// -------------------- problem dims --------------------
#define BATCH   4
#define SEQ     2048
#define DMODEL  1024
#define HEADS   16
#define HDIM    64
#define MROWS   (BATCH*SEQ)         // 8192
#define NBH     (BATCH*HEADS)       // 64
#define NQKV    (3*DMODEL)          // 3072
#define LOG2E   1.4426950408889634f

// -------------------- device scratch (static, no allocs) --------------------
__device__ __half g_Xh   [(size_t)MROWS * DMODEL];
__device__ __half g_WTqkv[(size_t)NQKV * DMODEL];     // rows: [Wq*log2e/32 | Wk | Wv] transposed
__device__ float  g_bqkv [NQKV];                      // [bq*log2e/32 | bk | bv]
__device__ __half g_WTo  [(size_t)DMODEL * DMODEL];
__device__ __half g_QKV  [(size_t)MROWS * NQKV];      // cols: [Q(scaled) | K | V]
__device__ __half g_Ctx  [(size_t)MROWS * DMODEL];

// -------------------- small helpers --------------------
__device__ __forceinline__ uint32_t smem_u32(const void* p) {
    uint32_t a;
    asm("{ .reg .u64 t; cvta.to.shared.u64 t, %1; cvt.u32.u64 %0, t; }" : "=r"(a) : "l"(p));
    return a;
}
__device__ __forceinline__ void cp16(void* s, const void* g) {
    uint32_t sa = smem_u32(s);
    asm volatile("cp.async.cg.shared.global [%0], [%1], 16;" :: "r"(sa), "l"(g) : "memory");
}
__device__ __forceinline__ void cp16_ca(void* s, const void* g) {   // L1-allocating
    uint32_t sa = smem_u32(s);
    asm volatile("cp.async.ca.shared.global [%0], [%1], 16;" :: "r"(sa), "l"(g) : "memory");
}
#define CP_COMMIT() asm volatile("cp.async.commit_group;" ::: "memory")
#define CP_WAIT0()  asm volatile("cp.async.wait_group 0;" ::: "memory")
#define CP_WAIT1()  asm volatile("cp.async.wait_group 1;" ::: "memory")

__device__ __forceinline__ void ldsm_x4(uint32_t* r, const void* p) {
    uint32_t a = smem_u32(p);
    asm volatile("ldmatrix.sync.aligned.m8n8.x4.shared.b16 {%0,%1,%2,%3}, [%4];"
                 : "=r"(r[0]), "=r"(r[1]), "=r"(r[2]), "=r"(r[3]) : "r"(a));
}
__device__ __forceinline__ void ldsm_x4_t(uint32_t* r, const void* p) {
    uint32_t a = smem_u32(p);
    asm volatile("ldmatrix.sync.aligned.m8n8.x4.trans.shared.b16 {%0,%1,%2,%3}, [%4];"
                 : "=r"(r[0]), "=r"(r[1]), "=r"(r[2]), "=r"(r[3]) : "r"(a));
}
__device__ __forceinline__ void mma16816(float* c, const uint32_t* a, const uint32_t* b) {
    asm volatile("mma.sync.aligned.m16n8k16.row.col.f32.f16.f16.f32 "
                 "{%0,%1,%2,%3}, {%4,%5,%6,%7}, {%8,%9}, {%0,%1,%2,%3};"
                 : "+f"(c[0]), "+f"(c[1]), "+f"(c[2]), "+f"(c[3])
                 : "r"(a[0]), "r"(a[1]), "r"(a[2]), "r"(a[3]), "r"(b[0]), "r"(b[1]));
}
// f16-accumulator variant: C/D are 2 regs of packed half2
__device__ __forceinline__ void mma16816h(uint32_t* c, const uint32_t* a, const uint32_t* b) {
    asm volatile("mma.sync.aligned.m16n8k16.row.col.f16.f16.f16.f16 "
                 "{%0,%1}, {%2,%3,%4,%5}, {%6,%7}, {%0,%1};"
                 : "+r"(c[0]), "+r"(c[1])
                 : "r"(a[0]), "r"(a[1]), "r"(a[2]), "r"(a[3]), "r"(b[0]), "r"(b[1]));
}
__device__ __forceinline__ void h2exp2(uint32_t& v) {
    asm("ex2.approx.f16x2 %0, %0;" : "+r"(v));
}

// -------------------- mma.sync GEMM: BK=64, 3-stage, 1 barrier/iter (round-14 form) --------------------
#define LDS 72          // 64 + 8 pad halves; ldmatrix conflict-free
#define STAGES 3

template<bool OUT_HALF>
__global__ __launch_bounds__(256, 2) void mma_gemm(
    const __half* __restrict__ A, const __half* __restrict__ B,
    const float* __restrict__ bias, float* __restrict__ Cf, __half* __restrict__ Ch,
    int lda, int ldb, int ldc, int Kdim)
{
    extern __shared__ __half sh[];
    __half* sA = sh;                        // [STAGES][128][LDS]
    __half* sB = sh + STAGES * 128 * LDS;

    const int tid = threadIdx.x;
    const int lane = tid & 31;
    const int w = tid >> 5;
    const int wm = w >> 2;
    const int wn = w & 3;

    const __half* Ab = A + (long long)blockIdx.y * 128 * lda;
    const __half* Bb = B + (long long)blockIdx.x * 128 * ldb;

    const int nChunks = Kdim >> 6;          // BK = 64

    auto loadStage = [&](int s, int k0) {
        __half* a0 = sA + s * 128 * LDS;
        __half* b0 = sB + s * 128 * LDS;
#pragma unroll
        for (int i = tid; i < 128 * 8; i += 256) {
            int row = i >> 3, c8 = (i & 7) * 8;
            cp16_ca(a0 + row * LDS + c8, Ab + (long long)row * lda + k0 + c8);  // A: L1-cached
            cp16(b0 + row * LDS + c8, Bb + (long long)row * ldb + k0 + c8);     // B: L2-only
        }
    };

    float acc[4][4][4];
#pragma unroll
    for (int mt = 0; mt < 4; mt++)
#pragma unroll
        for (int nt = 0; nt < 4; nt++)
#pragma unroll
            for (int j = 0; j < 4; j++) acc[mt][nt][j] = 0.f;

    loadStage(0, 0);  CP_COMMIT();
    loadStage(1, 64); CP_COMMIT();

    for (int i = 0; i < nChunks; i++) {
        CP_WAIT1();
        __syncthreads();
        if (i + 2 < nChunks) loadStage((i + 2) % STAGES, (i + 2) * 64);
        CP_COMMIT();

        const int s = i % STAGES;
        __half* a0 = sA + s * 128 * LDS;
        __half* b0 = sB + s * 128 * LDS;
#pragma unroll
        for (int kk = 0; kk < 64; kk += 16) {
            uint32_t af[4][4];
#pragma unroll
            for (int mt = 0; mt < 4; mt++)
                ldsm_x4(af[mt], a0 + (wm * 64 + mt * 16 + (lane & 15)) * LDS + kk + (lane >> 4) * 8);

            uint32_t bf[4][2];
#pragma unroll
            for (int p = 0; p < 2; p++) {
                uint32_t r[4];
                ldsm_x4(r, b0 + (wn * 32 + p * 16 + (lane & 7) + ((lane >> 4) & 1) * 8) * LDS
                              + kk + ((lane >> 3) & 1) * 8);
                bf[2 * p][0] = r[0]; bf[2 * p][1] = r[1];
                bf[2 * p + 1][0] = r[2]; bf[2 * p + 1][1] = r[3];
            }
#pragma unroll
            for (int mt = 0; mt < 4; mt++)
#pragma unroll
                for (int nt = 0; nt < 4; nt++)
                    mma16816(acc[mt][nt], af[mt], bf[nt]);
        }
    }

#pragma unroll
    for (int mt = 0; mt < 4; mt++) {
        const int gRow0 = blockIdx.y * 128 + wm * 64 + mt * 16 + (lane >> 2);
#pragma unroll
        for (int nt = 0; nt < 4; nt++) {
            const int gCol = blockIdx.x * 128 + wn * 32 + nt * 8 + (lane & 3) * 2;
            float b0 = bias[gCol], b1 = bias[gCol + 1];
            float v00 = acc[mt][nt][0] + b0;
            float v01 = acc[mt][nt][1] + b1;
            float v10 = acc[mt][nt][2] + b0;
            float v11 = acc[mt][nt][3] + b1;
            if (OUT_HALF) {
                __half2* p0 = (__half2*)(Ch + (long long)gRow0 * ldc + gCol);
                __half2* p1 = (__half2*)(Ch + (long long)(gRow0 + 8) * ldc + gCol);
                *p0 = __floats2half2_rn(v00, v01);
                *p1 = __floats2half2_rn(v10, v11);
            } else {
                float2* p0 = (float2*)(Cf + (long long)gRow0 * ldc + gCol);
                float2* p1 = (float2*)(Cf + (long long)(gRow0 + 8) * ldc + gCol);
                *p0 = make_float2(v00, v01);
                *p1 = make_float2(v10, v11);
            }
        }
    }
}

// -------------------- fused flash attention: KTILE=64, 2-stage, late prefetch --------------------
// QK in fp16 accumulators (C-layout == PV A-layout), exp2 via f16x2 in place,
// row sums via fp32 ones-MMA. Prefetch issued after the QK phase.
__global__ __launch_bounds__(256, 2) void flash_mma(
    const __half* __restrict__ QKV, __half* __restrict__ Ctx)
{
    __shared__ __align__(16) __half sK[2][64][72];
    __shared__ __align__(16) __half sV[2][64][72];

    const int tid = threadIdx.x, lane = tid & 31, w = tid >> 5;
    const int z = blockIdx.y, b = z / HEADS, h = z % HEADS;
    const int qt = blockIdx.x;
    const __half* Qb = QKV + (size_t)(b * SEQ + qt * 128) * NQKV + h * HDIM;
    const __half* Kb = QKV + (size_t)(b * SEQ) * NQKV + DMODEL + h * HDIM;
    const __half* Vb = QKV + (size_t)(b * SEQ) * NQKV + 2 * DMODEL + h * HDIM;

    __half (*sQ)[72] = (__half (*)[72])&sK[0][0][0];
    for (int i = tid; i < 128 * 8; i += 256) {
        int row = i >> 3, c8 = (i & 7) * 8;
        cp16(&sQ[row][c8], Qb + (size_t)row * NQKV + c8);
    }
    CP_COMMIT(); CP_WAIT0();
    __syncthreads();
    uint32_t qf[4][4];
#pragma unroll
    for (int kk = 0; kk < 4; kk++)
        ldsm_x4(qf[kk], &sQ[w * 16 + (lane & 15)][kk * 16 + (lane >> 4) * 8]);
    __syncthreads();

    float acc[8][4];
#pragma unroll
    for (int j = 0; j < 8; j++)
#pragma unroll
        for (int t = 0; t < 4; t++) acc[j][t] = 0.f;
    float sumacc[4] = {0.f, 0.f, 0.f, 0.f};
    const uint32_t ones2 = 0x3C003C00u;              // half2(1,1)
    const uint32_t onesb[2] = {ones2, ones2};

    auto loadKV = [&](int s, int kt) {
        const __half* Kt = Kb + (size_t)kt * 64 * NQKV;
        const __half* Vt = Vb + (size_t)kt * 64 * NQKV;
        for (int i = tid; i < 64 * 8; i += 256) {
            int row = i >> 3, c8 = (i & 7) * 8;
            cp16(&sK[s][row][c8], Kt + (size_t)row * NQKV + c8);
            cp16(&sV[s][row][c8], Vt + (size_t)row * NQKV + c8);
        }
    };
    loadKV(0, 0); CP_COMMIT();

    for (int kt = 0; kt < SEQ / 64; kt++) {
        CP_WAIT0();
        __syncthreads();
        const int s = kt & 1;

        // ---- QK scores in fp16 accumulators ----
        uint32_t scH[8][2];
#pragma unroll
        for (int j = 0; j < 8; j++) { scH[j][0] = 0u; scH[j][1] = 0u; }
#pragma unroll
        for (int kk = 0; kk < 4; kk++) {
#pragma unroll
            for (int p = 0; p < 4; p++) {
                uint32_t r[4];
                ldsm_x4(r, &sK[s][p * 16 + (lane & 7) + ((lane >> 4) & 1) * 8]
                              [kk * 16 + ((lane >> 3) & 1) * 8]);
                uint32_t b0[2] = {r[0], r[1]}, b1[2] = {r[2], r[3]};
                mma16816h(scH[2 * p], qf[kk], b0);
                mma16816h(scH[2 * p + 1], qf[kk], b1);
            }
        }

        // prefetch next K/V AFTER the QK phase (tensor pipe busy from barrier+0)
        if (kt + 1 < SEQ / 64) loadKV(s ^ 1, kt + 1);
        CP_COMMIT();

        // ---- exp2 in place (scores already in PV A-fragment layout) ----
        uint32_t pf[4][4];
#pragma unroll
        for (int kk = 0; kk < 4; kk++) {
            uint32_t v0 = scH[2 * kk][0], v1 = scH[2 * kk][1];
            uint32_t v2 = scH[2 * kk + 1][0], v3 = scH[2 * kk + 1][1];
            h2exp2(v0); h2exp2(v1); h2exp2(v2); h2exp2(v3);
            pf[kk][0] = v0; pf[kk][1] = v1; pf[kk][2] = v2; pf[kk][3] = v3;
        }
#pragma unroll
        for (int kk = 0; kk < 4; kk++)
            mma16816(sumacc, pf[kk], onesb);

#pragma unroll
        for (int kk = 0; kk < 4; kk++) {
#pragma unroll
            for (int p = 0; p < 4; p++) {
                uint32_t r[4];
                ldsm_x4_t(r, &sV[s][kk * 16 + (lane & 15)][p * 16 + (lane >> 4) * 8]);
                uint32_t b0[2] = {r[0], r[1]}, b1[2] = {r[2], r[3]};
                mma16816(acc[2 * p], pf[kk], b0);
                mma16816(acc[2 * p + 1], pf[kk], b1);
            }
        }
    }

    const float inv0 = 1.0f / sumacc[0], inv1 = 1.0f / sumacc[2];

    const int gr = b * SEQ + qt * 128 + w * 16 + (lane >> 2);
    const int gc0 = h * HDIM + (lane & 3) * 2;
#pragma unroll
    for (int j = 0; j < 8; j++) {
        __half* r0 = Ctx + (size_t)gr * DMODEL + gc0 + j * 8;
        __half* r1 = Ctx + (size_t)(gr + 8) * DMODEL + gc0 + j * 8;
        *(__half2*)r0 = __floats2half2_rn(acc[j][0] * inv0, acc[j][1] * inv0);
        *(__half2*)r1 = __floats2half2_rn(acc[j][2] * inv1, acc[j][3] * inv1);
    }
}

// -------------------- converts (single launch) --------------------
__global__ void conv_all_kernel(
    const float* __restrict__ X,
    const float* __restrict__ Wq, const float* __restrict__ Wk,
    const float* __restrict__ Wv, const float* __restrict__ Wo,
    const float* __restrict__ bq, const float* __restrict__ bk,
    const float* __restrict__ bv,
    __half* __restrict__ Xh,
    __half* __restrict__ WTqkv, __half* __restrict__ WTo,
    float* __restrict__ bqkv)
{
    const int zz = blockIdx.z;
    const int tloc = threadIdx.y * 32 + threadIdx.x;
    if (zz == 5) {
        const int nF4 = MROWS * DMODEL / 4;
        const int stride = 32 * 32 * 256;
        for (int i = (blockIdx.y * 32 + blockIdx.x) * 256 + tloc; i < nF4; i += stride) {
            float4 x = ((const float4*)X)[i];
            __half2 a = __floats2half2_rn(x.x, x.y);
            __half2 c = __floats2half2_rn(x.z, x.w);
            ((uint2*)Xh)[i] = make_uint2(*(uint32_t*)&a, *(uint32_t*)&c);
        }
        return;
    }
    if (zz == 4) {
        int i = (blockIdx.y * 32 + blockIdx.x) * 256 + tloc;
        if (i < DMODEL)            bqkv[i] = bq[i] * (LOG2E / 32.0f);
        else if (i < 2 * DMODEL)   bqkv[i] = bk[i - DMODEL];
        else if (i < 3 * DMODEL)   bqkv[i] = bv[i - 2 * DMODEL];
        return;
    }
    const float* W = (zz == 0) ? Wq : (zz == 1) ? Wk : (zz == 2) ? Wv : Wo;
    __half* WT = (zz == 3) ? WTo : WTqkv + (size_t)zz * DMODEL * DMODEL;
    const float scale = (zz == 0) ? (LOG2E / 32.0f) : 1.0f;

    __shared__ float tile[32][33];
    const int tx = threadIdx.x, ty = threadIdx.y;
    const int k0 = blockIdx.y * 32, n0 = blockIdx.x * 32;
#pragma unroll
    for (int j = 0; j < 4; j++)
        tile[ty + j * 8][tx] = W[(size_t)(k0 + ty + j * 8) * DMODEL + n0 + tx];
    __syncthreads();
#pragma unroll
    for (int j = 0; j < 4; j++) {
        int n = n0 + ty + j * 8, k = k0 + tx;
        WT[(size_t)n * DMODEL + k] = __float2half_rn(tile[tx][ty + j * 8] * scale);
    }
}

// -------------------- launch --------------------
extern "C" void kernel_launch(void* const* d_in, const int* in_sizes, int n_in,
                              void* d_out, int out_size)
{
    const float* X  = (const float*)d_in[0];
    const float* Wq = (const float*)d_in[1];
    const float* bq = (const float*)d_in[2];
    const float* Wk = (const float*)d_in[3];
    const float* bk = (const float*)d_in[4];
    const float* Wv = (const float*)d_in[5];
    const float* bv = (const float*)d_in[6];
    const float* Wo = (const float*)d_in[7];
    const float* bo = (const float*)d_in[8];
    float* out = (float*)d_out;

    __half *pXh, *pWTqkv, *pWTo, *pQKV, *pCtx;
    float *pbqkv;
    cudaGetSymbolAddress((void**)&pXh, g_Xh);
    cudaGetSymbolAddress((void**)&pWTqkv, g_WTqkv);
    cudaGetSymbolAddress((void**)&pbqkv, g_bqkv);
    cudaGetSymbolAddress((void**)&pWTo, g_WTo);
    cudaGetSymbolAddress((void**)&pQKV, g_QKV);
    cudaGetSymbolAddress((void**)&pCtx, g_Ctx);

    const int GEMM_SMEM = STAGES * 2 * 128 * LDS * (int)sizeof(__half);  // 110592
    cudaFuncSetAttribute(mma_gemm<true>,  cudaFuncAttributeMaxDynamicSharedMemorySize, GEMM_SMEM);
    cudaFuncSetAttribute(mma_gemm<false>, cudaFuncAttributeMaxDynamicSharedMemorySize, GEMM_SMEM);

    // converts (1 launch)
    dim3 cgrid(32, 32, 6), cblk(32, 8);
    conv_all_kernel<<<cgrid, cblk>>>(X, Wq, Wk, Wv, Wo, bq, bk, bv,
                                     pXh, pWTqkv, pWTo, pbqkv);

    // fused QKV projection
    dim3 pg(NQKV / 128, MROWS / 128, 1);
    mma_gemm<true><<<pg, 256, GEMM_SMEM>>>(pXh, pWTqkv, pbqkv, nullptr, pQKV,
        DMODEL, DMODEL, NQKV, DMODEL);

    // fused flash attention -> fp16 Ctx
    dim3 fg(SEQ / 128, NBH);
    flash_mma<<<fg, 256>>>(pQKV, pCtx);

    // out = Ctx @ Wo + bo
    dim3 og(DMODEL / 128, MROWS / 128, 1);
    mma_gemm<false><<<og, 256, GEMM_SMEM>>>(pCtx, pWTo, bo, out, nullptr,
        DMODEL, DMODEL, DMODEL, DMODEL);
}